// round 1
// baseline (speedup 1.0000x reference)
#include <cuda_runtime.h>
#include <mma.h>
#include <math.h>

using namespace nvcuda;

#define NBATCH 2
#define NT     2048
#define NDM    1024
#define NH     16
#define ND     64
#define QKVN   (NH * 5 * ND)   // 5120
#define BTOT   (NBATCH * NT)   // 4096

// Scratch (device-global; allocation-free per harness rules)
__device__ float g_qkv[(size_t)BTOT * QKVN];   // (B*T, 5120)
__device__ float g_attn[(size_t)BTOT * NDM];   // (B*T, 1024)

// ---------------------------------------------------------------------------
// TF32 wmma GEMM: C[M,N] = A[M,K] @ B[K,N], all row-major fp32.
// 256 threads, 8 warps in 2x4 grid, warp tile 64x32, block tile 128x128x16.
// ---------------------------------------------------------------------------
#define GBM 128
#define GBN 128
#define GBK 16
#define GLDA (GBK + 4)
#define GLDB (GBN + 4)

__global__ __launch_bounds__(256) void gemm_tf32_kernel(
    const float* __restrict__ A, const float* __restrict__ B,
    float* __restrict__ C, int M, int N, int K) {
  __shared__ float As[GBM * GLDA];
  __shared__ float Bs[GBK * GLDB];

  const int tid  = threadIdx.x;
  const int warp = tid >> 5;
  const int wm   = warp & 1;   // 0..1 -> 64 rows each
  const int wn   = warp >> 1;  // 0..3 -> 32 cols each
  const int bm   = blockIdx.y * GBM;
  const int bn   = blockIdx.x * GBN;

  wmma::fragment<wmma::accumulator, 16, 16, 8, float> acc[4][2];
#pragma unroll
  for (int i = 0; i < 4; i++)
#pragma unroll
    for (int j = 0; j < 2; j++) wmma::fill_fragment(acc[i][j], 0.0f);

  for (int k0 = 0; k0 < K; k0 += GBK) {
    for (int i = tid; i < GBM * GBK; i += 256) {
      int r = i >> 4, c = i & 15;
      As[r * GLDA + c] = wmma::__float_to_tf32(A[(size_t)(bm + r) * K + k0 + c]);
    }
    for (int i = tid; i < GBK * GBN; i += 256) {
      int r = i >> 7, c = i & 127;
      Bs[r * GLDB + c] = wmma::__float_to_tf32(B[(size_t)(k0 + r) * N + bn + c]);
    }
    __syncthreads();

#pragma unroll
    for (int kk = 0; kk < GBK; kk += 8) {
      wmma::fragment<wmma::matrix_a, 16, 16, 8, wmma::precision::tf32, wmma::row_major> af[4];
      wmma::fragment<wmma::matrix_b, 16, 16, 8, wmma::precision::tf32, wmma::row_major> bf[2];
#pragma unroll
      for (int i = 0; i < 4; i++)
        wmma::load_matrix_sync(af[i], &As[(wm * 64 + i * 16) * GLDA + kk], GLDA);
#pragma unroll
      for (int j = 0; j < 2; j++)
        wmma::load_matrix_sync(bf[j], &Bs[kk * GLDB + wn * 32 + j * 16], GLDB);
#pragma unroll
      for (int i = 0; i < 4; i++)
#pragma unroll
        for (int j = 0; j < 2; j++)
          wmma::mma_sync(acc[i][j], af[i], bf[j], acc[i][j]);
    }
    __syncthreads();
  }

#pragma unroll
  for (int i = 0; i < 4; i++)
#pragma unroll
    for (int j = 0; j < 2; j++)
      wmma::store_matrix_sync(
          &C[(size_t)(bm + wm * 64 + i * 16) * N + bn + wn * 32 + j * 16],
          acc[i][j], N, wmma::mem_row_major);
}

// ---------------------------------------------------------------------------
// Differential attention: one block per (b, h, 64-query tile). 128 threads.
// Two-pass softmax: pass1 = per-row (m,l) for both softmaxes; pass2 = combined
// probabilities (a1 - lam*a2) and P@V accumulation in wmma fragments.
// qkv layout per row: [q1(64) q2(64) k1(64) k2(64) v(64)] per head.
// ---------------------------------------------------------------------------
#define ALD 68  // 64 + 4 pad (multiple of 4 for wmma ldm)

__device__ __forceinline__ void compute_score_strips(
    const float* q1s, const float* q2s, const float* k1s, const float* k2s,
    float* s1s, float* s2s, int warp) {
  const int wr = warp * 16;
#pragma unroll
  for (int jt = 0; jt < 4; jt++) {
    wmma::fragment<wmma::accumulator, 16, 16, 8, float> sa1, sa2;
    wmma::fill_fragment(sa1, 0.0f);
    wmma::fill_fragment(sa2, 0.0f);
#pragma unroll
    for (int kk = 0; kk < 64; kk += 8) {
      wmma::fragment<wmma::matrix_a, 16, 16, 8, wmma::precision::tf32, wmma::row_major> a1, a2;
      wmma::fragment<wmma::matrix_b, 16, 16, 8, wmma::precision::tf32, wmma::col_major> b1, b2;
      wmma::load_matrix_sync(a1, &q1s[wr * ALD + kk], ALD);
      wmma::load_matrix_sync(a2, &q2s[wr * ALD + kk], ALD);
      wmma::load_matrix_sync(b1, &k1s[(jt * 16) * ALD + kk], ALD);
      wmma::load_matrix_sync(b2, &k2s[(jt * 16) * ALD + kk], ALD);
      wmma::mma_sync(sa1, a1, b1, sa1);
      wmma::mma_sync(sa2, a2, b2, sa2);
    }
    wmma::store_matrix_sync(&s1s[wr * ALD + jt * 16], sa1, ALD, wmma::mem_row_major);
    wmma::store_matrix_sync(&s2s[wr * ALD + jt * 16], sa2, ALD, wmma::mem_row_major);
  }
}

__global__ __launch_bounds__(128) void attn_kernel(
    const float* __restrict__ lam_p, float* __restrict__ attn_out) {
  extern __shared__ float sm[];
  float* q1s = sm;
  float* q2s = q1s + 64 * ALD;
  float* k1s = q2s + 64 * ALD;
  float* k2s = k1s + 64 * ALD;
  float* vs  = k2s + 64 * ALD;
  float* s1s = vs  + 64 * ALD;
  float* s2s = s1s + 64 * ALD;
  float* m1  = s2s + 64 * ALD;
  float* l1  = m1 + 64;
  float* m2  = l1 + 64;
  float* l2  = m2 + 64;

  const int tid  = threadIdx.x;
  const int warp = tid >> 5;
  const int b    = blockIdx.z;
  const int h    = blockIdx.y;
  const int i0   = blockIdx.x * 64;
  const float scale = 0.125f;  // 1/sqrt(64)
  const float lamc  = fminf(fmaxf(lam_p[h], 0.0f), 1.0f);

  const float* base = g_qkv + (size_t)b * NT * QKVN + h * (5 * ND);

  // Load Q tiles once
  for (int idx = tid; idx < 64 * 64; idx += 128) {
    int r = idx >> 6, c = idx & 63;
    const float* row = base + (size_t)(i0 + r) * QKVN;
    q1s[r * ALD + c] = wmma::__float_to_tf32(row[c]);
    q2s[r * ALD + c] = wmma::__float_to_tf32(row[ND + c]);
  }
  if (tid < 64) { m1[tid] = -1e30f; l1[tid] = 0.0f; }
  else          { m2[tid - 64] = -1e30f; l2[tid - 64] = 0.0f; }
  __syncthreads();

  // ---------------- Pass 1: softmax statistics ----------------
  for (int j0 = 0; j0 <= i0; j0 += 64) {
    for (int idx = tid; idx < 64 * 64; idx += 128) {
      int r = idx >> 6, c = idx & 63;
      const float* row = base + (size_t)(j0 + r) * QKVN;
      k1s[r * ALD + c] = wmma::__float_to_tf32(row[2 * ND + c]);
      k2s[r * ALD + c] = wmma::__float_to_tf32(row[3 * ND + c]);
    }
    __syncthreads();
    compute_score_strips(q1s, q2s, k1s, k2s, s1s, s2s, warp);
    __syncthreads();
    {
      int r = tid & 63;
      float* ss = (tid < 64) ? s1s : s2s;
      float* mP = (tid < 64) ? m1 : m2;
      float* lP = (tid < 64) ? l1 : l2;
      int jmax = i0 + r - j0 + 1;
      if (jmax > 64) jmax = 64;
      float mold = mP[r], mt = mold;
      for (int c = 0; c < jmax; c++) mt = fmaxf(mt, ss[r * ALD + c] * scale);
      float l = lP[r] * __expf(mold - mt);
      for (int c = 0; c < jmax; c++) l += __expf(ss[r * ALD + c] * scale - mt);
      mP[r] = mt;
      lP[r] = l;
    }
    __syncthreads();
  }
  if (tid < 64) l1[tid] = 1.0f / l1[tid];
  else          l2[tid - 64] = 1.0f / l2[tid - 64];
  __syncthreads();

  // ---------------- Pass 2: combined probs + PV ----------------
  wmma::fragment<wmma::accumulator, 16, 16, 8, float> oacc[4];
#pragma unroll
  for (int i = 0; i < 4; i++) wmma::fill_fragment(oacc[i], 0.0f);

  for (int j0 = 0; j0 <= i0; j0 += 64) {
    for (int idx = tid; idx < 64 * 64; idx += 128) {
      int r = idx >> 6, c = idx & 63;
      const float* row = base + (size_t)(j0 + r) * QKVN;
      k1s[r * ALD + c] = wmma::__float_to_tf32(row[2 * ND + c]);
      k2s[r * ALD + c] = wmma::__float_to_tf32(row[3 * ND + c]);
      vs[r * ALD + c]  = wmma::__float_to_tf32(row[4 * ND + c]);
    }
    __syncthreads();
    compute_score_strips(q1s, q2s, k1s, k2s, s1s, s2s, warp);
    __syncthreads();
    // combined probability written over s1s
    for (int idx = tid; idx < 64 * 64; idx += 128) {
      int r = idx >> 6, c = idx & 63;
      float p = 0.0f;
      if (j0 + c <= i0 + r) {
        p = __expf(s1s[r * ALD + c] * scale - m1[r]) * l1[r]
          - lamc * __expf(s2s[r * ALD + c] * scale - m2[r]) * l2[r];
      }
      s1s[r * ALD + c] = wmma::__float_to_tf32(p);
    }
    __syncthreads();
    // P (16x64 per warp) @ V (64x64) -> accumulate 16x64
    {
      const int wr = warp * 16;
#pragma unroll
      for (int kk = 0; kk < 64; kk += 8) {
        wmma::fragment<wmma::matrix_a, 16, 16, 8, wmma::precision::tf32, wmma::row_major> pa;
        wmma::load_matrix_sync(pa, &s1s[wr * ALD + kk], ALD);
#pragma unroll
        for (int dt = 0; dt < 4; dt++) {
          wmma::fragment<wmma::matrix_b, 16, 16, 8, wmma::precision::tf32, wmma::row_major> vb;
          wmma::load_matrix_sync(vb, &vs[kk * ALD + dt * 16], ALD);
          wmma::mma_sync(oacc[dt], pa, vb, oacc[dt]);
        }
      }
    }
    __syncthreads();
  }

  // store: attn_out[(b*T + i) * 1024 + h*64 + d]
  {
    const int wr = warp * 16;
#pragma unroll
    for (int dt = 0; dt < 4; dt++)
      wmma::store_matrix_sync(
          &attn_out[(size_t)(b * NT + i0 + wr) * NDM + h * ND + dt * 16],
          oacc[dt], NDM, wmma::mem_row_major);
  }
}

// ---------------------------------------------------------------------------
// Launch
// ---------------------------------------------------------------------------
#define ATTN_SMEM ((7 * 64 * ALD + 4 * 64) * (int)sizeof(float))  // 122880 B

extern "C" void kernel_launch(void* const* d_in, const int* in_sizes, int n_in,
                              void* d_out, int out_size) {
  const float* x    = (const float*)d_in[0];
  // d_in[1] = mask: exact causal additive mask; handled analytically.
  const float* Wqkv = (const float*)d_in[2];
  const float* Wout = (const float*)d_in[3];
  const float* lam  = (const float*)d_in[4];
  float* out = (float*)d_out;

  float *qkv_d = nullptr, *attn_d = nullptr;
  cudaGetSymbolAddress((void**)&qkv_d, g_qkv);
  cudaGetSymbolAddress((void**)&attn_d, g_attn);

  // 1) qkv = x @ W_qkv : (4096,1024) x (1024,5120)
  {
    dim3 grid(QKVN / GBN, BTOT / GBM);  // (40, 32)
    gemm_tf32_kernel<<<grid, 256>>>(x, Wqkv, qkv_d, BTOT, QKVN, NDM);
  }

  // 2) differential attention
  {
    cudaFuncSetAttribute(attn_kernel, cudaFuncAttributeMaxDynamicSharedMemorySize,
                         ATTN_SMEM);
    dim3 grid(NT / 64, NH, NBATCH);  // (32, 16, 2)
    attn_kernel<<<grid, 128, ATTN_SMEM>>>(lam, attn_d);
  }

  // 3) out = attn @ W_out : (4096,1024) x (1024,1024)
  {
    dim3 grid(NDM / GBN, BTOT / GBM);  // (8, 32)
    gemm_tf32_kernel<<<grid, 256>>>(attn_d, Wout, out, BTOT, NDM, NDM);
  }
}

// round 2
// speedup vs baseline: 1.6617x; 1.6617x over previous
#include <cuda_runtime.h>
#include <mma.h>
#include <math.h>

using namespace nvcuda;

#define NBATCH 2
#define NT     2048
#define NDM    1024
#define NH     16
#define ND     64
#define QKVN   (NH * 5 * ND)   // 5120
#define BTOT   (NBATCH * NT)   // 4096

__device__ float g_qkv[(size_t)BTOT * QKVN];   // (B*T, 5120)
__device__ float g_attn[(size_t)BTOT * NDM];   // (B*T, 1024)

__device__ __forceinline__ float tf32r(float x) { return wmma::__float_to_tf32(x); }

// ---------------------------------------------------------------------------
// TF32 wmma GEMM, double-buffered. C[M,N] = A[M,K] @ B[K,N], row-major fp32.
// 256 threads, 8 warps 2x4, warp tile 64x32, block tile 128x128x32.
// ---------------------------------------------------------------------------
#define GBM 128
#define GBN 128
#define GBK 32
#define GLDA 36
#define GLDB 132

__global__ __launch_bounds__(256) void gemm_tf32_kernel(
    const float* __restrict__ A, const float* __restrict__ B,
    float* __restrict__ C, int M, int N, int K) {
  __shared__ float As[2][GBM * GLDA];
  __shared__ float Bs[2][GBK * GLDB];

  const int tid  = threadIdx.x;
  const int warp = tid >> 5;
  const int wm   = warp & 1;
  const int wn   = warp >> 1;
  const int bm   = blockIdx.y * GBM;
  const int bn   = blockIdx.x * GBN;

  wmma::fragment<wmma::accumulator, 16, 16, 8, float> acc[4][2];
#pragma unroll
  for (int i = 0; i < 4; i++)
#pragma unroll
    for (int j = 0; j < 2; j++) wmma::fill_fragment(acc[i][j], 0.0f);

  float4 ra[4], rb[4];

  // ldg for tile at k0
#define GEMM_LDG(k0)                                                        \
  {                                                                         \
    _Pragma("unroll") for (int i = 0; i < 4; i++) {                         \
      int f = tid + i * 256;                                                \
      int r = f >> 3, c = (f & 7) * 4;                                      \
      ra[i] = *(const float4*)&A[(size_t)(bm + r) * K + (k0) + c];          \
    }                                                                       \
    _Pragma("unroll") for (int i = 0; i < 4; i++) {                         \
      int f = tid + i * 256;                                                \
      int r = f >> 5, c = (f & 31) * 4;                                     \
      rb[i] = *(const float4*)&B[(size_t)((k0) + r) * N + bn + c];          \
    }                                                                       \
  }

#define GEMM_STS(bufi)                                                      \
  {                                                                         \
    _Pragma("unroll") for (int i = 0; i < 4; i++) {                         \
      int f = tid + i * 256;                                                \
      int r = f >> 3, c = (f & 7) * 4;                                      \
      float4 v = ra[i];                                                     \
      v.x = tf32r(v.x); v.y = tf32r(v.y); v.z = tf32r(v.z); v.w = tf32r(v.w); \
      *(float4*)&As[bufi][r * GLDA + c] = v;                                \
    }                                                                       \
    _Pragma("unroll") for (int i = 0; i < 4; i++) {                         \
      int f = tid + i * 256;                                                \
      int r = f >> 5, c = (f & 31) * 4;                                     \
      float4 v = rb[i];                                                     \
      v.x = tf32r(v.x); v.y = tf32r(v.y); v.z = tf32r(v.z); v.w = tf32r(v.w); \
      *(float4*)&Bs[bufi][r * GLDB + c] = v;                                \
    }                                                                       \
  }

  GEMM_LDG(0);
  GEMM_STS(0);
  __syncthreads();

  int buf = 0;
  for (int k0 = 0; k0 < K; k0 += GBK) {
    const bool has_next = (k0 + GBK) < K;
    if (has_next) GEMM_LDG(k0 + GBK);

#pragma unroll
    for (int kk = 0; kk < GBK; kk += 8) {
      wmma::fragment<wmma::matrix_a, 16, 16, 8, wmma::precision::tf32, wmma::row_major> af[4];
      wmma::fragment<wmma::matrix_b, 16, 16, 8, wmma::precision::tf32, wmma::row_major> bf[2];
#pragma unroll
      for (int i = 0; i < 4; i++)
        wmma::load_matrix_sync(af[i], &As[buf][(wm * 64 + i * 16) * GLDA + kk], GLDA);
#pragma unroll
      for (int j = 0; j < 2; j++)
        wmma::load_matrix_sync(bf[j], &Bs[buf][kk * GLDB + wn * 32 + j * 16], GLDB);
#pragma unroll
      for (int i = 0; i < 4; i++)
#pragma unroll
        for (int j = 0; j < 2; j++)
          wmma::mma_sync(acc[i][j], af[i], bf[j], acc[i][j]);
    }

    if (has_next) GEMM_STS(buf ^ 1);
    __syncthreads();
    buf ^= 1;
  }

#pragma unroll
  for (int i = 0; i < 4; i++)
#pragma unroll
    for (int j = 0; j < 2; j++)
      wmma::store_matrix_sync(
          &C[(size_t)(bm + wm * 64 + i * 16) * N + bn + wn * 32 + j * 16],
          acc[i][j], N, wmma::mem_row_major);
}

// ---------------------------------------------------------------------------
// Single-pass differential attention, no-max softmax.
// Block: 256 threads (8 warps), 128-query tile, 64-key tiles.
// S tile is warp-private by 16-row strip -> only 2 block syncs per k-tile.
// ---------------------------------------------------------------------------
#define ALD 68

using FragAcc = wmma::fragment<wmma::accumulator, 16, 16, 8, float>;

__device__ __forceinline__ void attn_pass(
    const float* __restrict__ qs, const float* __restrict__ ks,
    const float* __restrict__ vsd, float* __restrict__ ss,
    FragAcc O[4], float& lacc,
    int wr, int r_el, int cb, int i0, int j0, bool needmask) {
  // ---- S strip = Q(strip) @ K^T ----
#pragma unroll
  for (int jt = 0; jt < 4; jt++) {
    FragAcc sacc;
    wmma::fill_fragment(sacc, 0.0f);
#pragma unroll
    for (int kk = 0; kk < 64; kk += 8) {
      wmma::fragment<wmma::matrix_a, 16, 16, 8, wmma::precision::tf32, wmma::row_major> a;
      wmma::fragment<wmma::matrix_b, 16, 16, 8, wmma::precision::tf32, wmma::col_major> bfr;
      wmma::load_matrix_sync(a, &qs[wr * ALD + kk], ALD);
      wmma::load_matrix_sync(bfr, &ks[(jt * 16) * ALD + kk], ALD);
      wmma::mma_sync(sacc, a, bfr, sacc);
    }
    wmma::store_matrix_sync(&ss[wr * ALD + jt * 16], sacc, ALD, wmma::mem_row_major);
  }
  __syncwarp();

  // ---- exp (scale folded into Q), causal mask, row-sum partial ----
  {
    float* sr = &ss[r_el * ALD + cb];
    const int lim = i0 + r_el - j0 - cb;  // valid iff c <= lim
    if (needmask) {
#pragma unroll
      for (int c = 0; c < 32; c += 4) {
        float4 s4 = *(float4*)&sr[c];
        float p0 = __expf(s4.x), p1 = __expf(s4.y);
        float p2 = __expf(s4.z), p3 = __expf(s4.w);
        p0 = (c + 0 <= lim) ? p0 : 0.0f;
        p1 = (c + 1 <= lim) ? p1 : 0.0f;
        p2 = (c + 2 <= lim) ? p2 : 0.0f;
        p3 = (c + 3 <= lim) ? p3 : 0.0f;
        lacc += (p0 + p1) + (p2 + p3);
        s4.x = tf32r(p0); s4.y = tf32r(p1); s4.z = tf32r(p2); s4.w = tf32r(p3);
        *(float4*)&sr[c] = s4;
      }
    } else {
#pragma unroll
      for (int c = 0; c < 32; c += 4) {
        float4 s4 = *(float4*)&sr[c];
        float p0 = __expf(s4.x), p1 = __expf(s4.y);
        float p2 = __expf(s4.z), p3 = __expf(s4.w);
        lacc += (p0 + p1) + (p2 + p3);
        s4.x = tf32r(p0); s4.y = tf32r(p1); s4.z = tf32r(p2); s4.w = tf32r(p3);
        *(float4*)&sr[c] = s4;
      }
    }
  }
  __syncwarp();

  // ---- O(strip) += P(strip) @ V ----
#pragma unroll
  for (int kk = 0; kk < 64; kk += 8) {
    wmma::fragment<wmma::matrix_a, 16, 16, 8, wmma::precision::tf32, wmma::row_major> pa;
    wmma::load_matrix_sync(pa, &ss[wr * ALD + kk], ALD);
#pragma unroll
    for (int dt = 0; dt < 4; dt++) {
      wmma::fragment<wmma::matrix_b, 16, 16, 8, wmma::precision::tf32, wmma::row_major> vb;
      wmma::load_matrix_sync(vb, &vsd[kk * ALD + dt * 16], ALD);
      wmma::mma_sync(O[dt], pa, vb, O[dt]);
    }
  }
  __syncwarp();
}

__global__ __launch_bounds__(256) void attn_kernel(
    const float* __restrict__ lam_p, float* __restrict__ attn_out) {
  extern __shared__ float sm[];
  float* q1s = sm;                   // 128 x ALD
  float* q2s = q1s + 128 * ALD;      // 128 x ALD
  float* kks = q2s + 128 * ALD;      // 128 x ALD  (K1: rows 0-63, K2: rows 64-127)
  float* vs  = kks + 128 * ALD;      // 64 x ALD
  float* ss  = vs + 64 * ALD;        // 128 x ALD

  const int tid  = threadIdx.x;
  const int warp = tid >> 5;
  const int wr   = warp * 16;
  const int b    = blockIdx.z;
  const int h    = blockIdx.y;
  const int i0   = (int)(gridDim.x - 1 - blockIdx.x) * 128;  // heavy blocks first
  const float lamc = fminf(fmaxf(lam_p[h], 0.0f), 1.0f);
  const float scale = 0.125f;  // 1/sqrt(64), folded into Q

  const float* base = g_qkv + (size_t)b * NT * QKVN + h * (5 * ND);

  // Load Q1, Q2 (scaled + tf32-rounded)
#pragma unroll
  for (int i = 0; i < 16; i++) {
    int f = tid + i * 256;
    int mat = f >> 11, r = (f >> 4) & 127, c = (f & 15) * 4;
    const float4 v = *(const float4*)&base[(size_t)(i0 + r) * QKVN + mat * ND + c];
    float4 o;
    o.x = tf32r(v.x * scale); o.y = tf32r(v.y * scale);
    o.z = tf32r(v.z * scale); o.w = tf32r(v.w * scale);
    *(float4*)&((mat ? q2s : q1s)[r * ALD + c]) = o;
  }

  FragAcc O1[4], O2[4];
#pragma unroll
  for (int i = 0; i < 4; i++) {
    wmma::fill_fragment(O1[i], 0.0f);
    wmma::fill_fragment(O2[i], 0.0f);
  }
  float l1acc = 0.0f, l2acc = 0.0f;
  const int r_el = tid >> 1;
  const int cb   = (tid & 1) * 32;

  const int ntiles = i0 / 64 + 2;
  for (int t = 0; t < ntiles; t++) {
    const int j0 = t * 64;
    __syncthreads();  // all warps done with previous K/V (and Q load on t=0 ordered below)
    // Load K1, K2, V
#pragma unroll
    for (int i = 0; i < 12; i++) {
      int f = tid + i * 256;
      int mat = f >> 10, r = (f >> 4) & 63, c = (f & 15) * 4;
      const float4 v = *(const float4*)&base[(size_t)(j0 + r) * QKVN + (2 + mat) * ND + c];
      float* dst = (mat == 0 ? kks : (mat == 1 ? kks + 64 * ALD : vs)) + r * ALD + c;
      float4 o;
      o.x = tf32r(v.x); o.y = tf32r(v.y); o.z = tf32r(v.z); o.w = tf32r(v.w);
      *(float4*)dst = o;
    }
    __syncthreads();

    const bool needmask = (j0 + 63 > i0);
    attn_pass(q1s, kks, vs, ss, O1, l1acc, wr, r_el, cb, i0, j0, needmask);
    attn_pass(q2s, kks + 64 * ALD, vs, ss, O2, l2acc, wr, r_el, cb, i0, j0, needmask);
  }

  __syncthreads();  // all warps done reading K/V before finalize reuses kks

  // Park O1 in ss strip, O2 in kks strip (both warp-private rows)
#pragma unroll
  for (int dt = 0; dt < 4; dt++) {
    wmma::store_matrix_sync(&ss[wr * ALD + dt * 16], O1[dt], ALD, wmma::mem_row_major);
    wmma::store_matrix_sync(&kks[wr * ALD + dt * 16], O2[dt], ALD, wmma::mem_row_major);
  }
  __syncwarp();

  const float l1 = l1acc + __shfl_xor_sync(0xFFFFFFFFu, l1acc, 1);
  const float l2 = l2acc + __shfl_xor_sync(0xFFFFFFFFu, l2acc, 1);
  const float inv1 = 1.0f / l1;
  const float inv2 = lamc / l2;

  const float* o1r = &ss[r_el * ALD + cb];
  const float* o2r = &kks[r_el * ALD + cb];
  float* outp = attn_out + (size_t)(b * NT + i0 + r_el) * NDM + h * ND + cb;
#pragma unroll
  for (int c = 0; c < 32; c += 4) {
    float4 a = *(const float4*)&o1r[c];
    float4 d = *(const float4*)&o2r[c];
    float4 o;
    o.x = a.x * inv1 - d.x * inv2;
    o.y = a.y * inv1 - d.y * inv2;
    o.z = a.z * inv1 - d.z * inv2;
    o.w = a.w * inv1 - d.w * inv2;
    *(float4*)&outp[c] = o;
  }
}

// ---------------------------------------------------------------------------
#define ATTN_SMEM ((4 * 128 * ALD + 64 * ALD) * (int)sizeof(float))  // 156,672 B

extern "C" void kernel_launch(void* const* d_in, const int* in_sizes, int n_in,
                              void* d_out, int out_size) {
  const float* x    = (const float*)d_in[0];
  // d_in[1] = mask: exact causal additive mask; handled analytically.
  const float* Wqkv = (const float*)d_in[2];
  const float* Wout = (const float*)d_in[3];
  const float* lam  = (const float*)d_in[4];
  float* out = (float*)d_out;

  float *qkv_d = nullptr, *attn_d = nullptr;
  cudaGetSymbolAddress((void**)&qkv_d, g_qkv);
  cudaGetSymbolAddress((void**)&attn_d, g_attn);

  // 1) qkv = x @ W_qkv : (4096,1024) x (1024,5120)
  {
    dim3 grid(QKVN / GBN, BTOT / GBM);  // (40, 32)
    gemm_tf32_kernel<<<grid, 256>>>(x, Wqkv, qkv_d, BTOT, QKVN, NDM);
  }

  // 2) differential attention (single pass)
  {
    cudaFuncSetAttribute(attn_kernel, cudaFuncAttributeMaxDynamicSharedMemorySize,
                         ATTN_SMEM);
    dim3 grid(NT / 128, NH, NBATCH);  // (16, 16, 2)
    attn_kernel<<<grid, 256, ATTN_SMEM>>>(lam, attn_d);
  }

  // 3) out = attn @ W_out : (4096,1024) x (1024,1024)
  {
    dim3 grid(NDM / GBN, BTOT / GBM);  // (8, 32)
    gemm_tf32_kernel<<<grid, 256>>>(attn_d, Wout, out, BTOT, NDM, NDM);
  }
}

// round 4
// speedup vs baseline: 1.8592x; 1.1188x over previous
#include <cuda_runtime.h>
#include <mma.h>
#include <math.h>
#include <cstdint>

using namespace nvcuda;

#define NBATCH 2
#define NT     2048
#define NDM    1024
#define NH     16
#define ND     64
#define QKVN   (NH * 5 * ND)   // 5120
#define BTOT   (NBATCH * NT)   // 4096

// Scratch (device-global; allocation-free per harness rules)
__device__ float g_qkv[(size_t)BTOT * QKVN];    // tf32-rounded, q-scaled
__device__ float g_attn[(size_t)BTOT * NDM];    // tf32-rounded
__device__ float g_x  [(size_t)BTOT * NDM];     // tf32-rounded x
__device__ float g_wq [(size_t)NDM * QKVN];     // tf32-rounded W_qkv
__device__ float g_wo [(size_t)NDM * NDM];      // tf32-rounded W_out

__device__ __forceinline__ float tf32r(float x) { return wmma::__float_to_tf32(x); }

__device__ __forceinline__ uint32_t smem_u32(const void* p) {
  uint32_t a;
  asm("{ .reg .u64 t; cvta.to.shared.u64 t, %1; cvt.u32.u64 %0, t; }"
      : "=r"(a) : "l"(p));
  return a;
}

#define CP_ASYNC16(dst, src) \
  asm volatile("cp.async.cg.shared.global [%0], [%1], 16;" :: "r"(dst), "l"(src))
#define CP_COMMIT() asm volatile("cp.async.commit_group;" ::: "memory")
__device__ __forceinline__ void cp_wait(bool last) {
  if (last) asm volatile("cp.async.wait_group 0;" ::: "memory");
  else      asm volatile("cp.async.wait_group 1;" ::: "memory");
}

// ---------------------------------------------------------------------------
// tf32 pre-round kernel (float4 grid-stride)
// ---------------------------------------------------------------------------
__global__ void round_tf32_kernel(const float* __restrict__ in,
                                  float* __restrict__ out, int n4) {
  int i = blockIdx.x * blockDim.x + threadIdx.x;
  if (i < n4) {
    float4 v = ((const float4*)in)[i];
    v.x = tf32r(v.x); v.y = tf32r(v.y); v.z = tf32r(v.z); v.w = tf32r(v.w);
    ((float4*)out)[i] = v;
  }
}

// ---------------------------------------------------------------------------
// TF32 wmma GEMM, cp.async 3-stage. Inputs pre-rounded to tf32.
// C[M,N] = A[M,K] @ B[K,N], row-major. Block 128x128x32, 256 thr, 8 warps 2x4.
// mode 0: plain fp32 store. mode 1: qkv epilogue (scale q cols, tf32-round).
// ---------------------------------------------------------------------------
#define TMM 128
#define TNN 128
#define TKK 32
#define LDA 36
#define LDB 132
#define A_STG (TMM * LDA)   // 4608 floats
#define B_STG (TKK * LDB)   // 4224 floats
#define GEMM_SMEM (3 * (A_STG + B_STG) * (int)sizeof(float))  // 105,984 B
#define LDS 132             // epilogue staging stride

__global__ __launch_bounds__(256, 2) void gemm_tc(
    const float* __restrict__ A, const float* __restrict__ B,
    float* __restrict__ C, int M, int N, int K, int mode) {
  extern __shared__ float smg[];
  float* Asm = smg;
  float* Bsm = smg + 3 * A_STG;
  const uint32_t sA = smem_u32(Asm);
  const uint32_t sB = smem_u32(Bsm);

  const int tid  = threadIdx.x;
  const int warp = tid >> 5;
  const int wm   = warp & 1;
  const int wn   = warp >> 1;
  const int bm   = blockIdx.y * TMM;
  const int bn   = blockIdx.x * TNN;

#define G_ISSUE(k0, s)                                                         \
  {                                                                            \
    uint32_t aB = sA + (uint32_t)(s) * (A_STG * 4);                            \
    uint32_t bB = sB + (uint32_t)(s) * (B_STG * 4);                            \
    _Pragma("unroll") for (int j = 0; j < 4; j++) {                            \
      int f = tid + j * 256;                                                   \
      int r = f >> 3, c4 = (f & 7) * 4;                                        \
      CP_ASYNC16(aB + (uint32_t)(r * LDA + c4) * 4,                            \
                 &A[(size_t)(bm + r) * K + (k0) + c4]);                        \
    }                                                                          \
    _Pragma("unroll") for (int j = 0; j < 4; j++) {                            \
      int f = tid + j * 256;                                                   \
      int r = f >> 5, c4 = (f & 31) * 4;                                       \
      CP_ASYNC16(bB + (uint32_t)(r * LDB + c4) * 4,                            \
                 &B[(size_t)((k0) + r) * N + bn + c4]);                        \
    }                                                                          \
    CP_COMMIT();                                                               \
  }

  wmma::fragment<wmma::accumulator, 16, 16, 8, float> acc[4][2];
#pragma unroll
  for (int i = 0; i < 4; i++)
#pragma unroll
    for (int j = 0; j < 2; j++) wmma::fill_fragment(acc[i][j], 0.0f);

  G_ISSUE(0, 0);
  G_ISSUE(TKK, 1);

  const int niter = K / TKK;
  for (int it = 0; it < niter; it++) {
    cp_wait(it == niter - 1);
    __syncthreads();
    if (it + 2 < niter) G_ISSUE((it + 2) * TKK, (it + 2) % 3);

    const float* As_ = Asm + (it % 3) * A_STG;
    const float* Bs_ = Bsm + (it % 3) * B_STG;
#pragma unroll
    for (int kk = 0; kk < TKK; kk += 8) {
      wmma::fragment<wmma::matrix_a, 16, 16, 8, wmma::precision::tf32, wmma::row_major> af[4];
      wmma::fragment<wmma::matrix_b, 16, 16, 8, wmma::precision::tf32, wmma::row_major> bf[2];
#pragma unroll
      for (int i = 0; i < 4; i++)
        wmma::load_matrix_sync(af[i], &As_[(wm * 64 + i * 16) * LDA + kk], LDA);
#pragma unroll
      for (int j = 0; j < 2; j++)
        wmma::load_matrix_sync(bf[j], &Bs_[kk * LDB + wn * 32 + j * 16], LDB);
#pragma unroll
      for (int i = 0; i < 4; i++)
#pragma unroll
        for (int j = 0; j < 2; j++)
          wmma::mma_sync(acc[i][j], af[i], bf[j], acc[i][j]);
    }
  }

  // epilogue: stage accum in smem, then coalesced write with mode transform
  __syncthreads();
#pragma unroll
  for (int i = 0; i < 4; i++)
#pragma unroll
    for (int j = 0; j < 2; j++)
      wmma::store_matrix_sync(&smg[(wm * 64 + i * 16) * LDS + wn * 32 + j * 16],
                              acc[i][j], LDS, wmma::mem_row_major);
  __syncthreads();

#pragma unroll
  for (int i = 0; i < 16; i++) {
    int f = tid + i * 256;
    int r = f >> 5, c4 = (f & 31) * 4;
    float4 v = *(const float4*)&smg[r * LDS + c4];
    if (mode == 1) {
      int gc = bn + c4;
      float s = ((gc % 320) < 128) ? 0.125f : 1.0f;
      v.x = tf32r(v.x * s); v.y = tf32r(v.y * s);
      v.z = tf32r(v.z * s); v.w = tf32r(v.w * s);
    }
    *(float4*)&C[(size_t)(bm + r) * N + bn + c4] = v;
  }
}

// ---------------------------------------------------------------------------
// Single-pass differential attention, no-max softmax, cp.async K/V pipeline.
// g_qkv is pre-rounded tf32 with scale folded into q columns.
// Block: 256 threads (8 warps), 128-query tile, 64-key tiles, 2 K/V buffers.
// ---------------------------------------------------------------------------
#define ALD 68
#define KV_STG (3 * 64 * ALD)  // floats per K/V stage

using FragAcc = wmma::fragment<wmma::accumulator, 16, 16, 8, float>;

__device__ __forceinline__ void attn_pass(
    const float* __restrict__ qs, const float* __restrict__ ks,
    const float* __restrict__ vsd, float* __restrict__ ss,
    FragAcc O[4], float& lacc,
    int wr, int r_el, int cb, int i0, int j0, bool needmask) {
#pragma unroll
  for (int jt = 0; jt < 4; jt++) {
    FragAcc sacc;
    wmma::fill_fragment(sacc, 0.0f);
#pragma unroll
    for (int kk = 0; kk < 64; kk += 8) {
      wmma::fragment<wmma::matrix_a, 16, 16, 8, wmma::precision::tf32, wmma::row_major> a;
      wmma::fragment<wmma::matrix_b, 16, 16, 8, wmma::precision::tf32, wmma::col_major> bfr;
      wmma::load_matrix_sync(a, &qs[wr * ALD + kk], ALD);
      wmma::load_matrix_sync(bfr, &ks[(jt * 16) * ALD + kk], ALD);
      wmma::mma_sync(sacc, a, bfr, sacc);
    }
    wmma::store_matrix_sync(&ss[wr * ALD + jt * 16], sacc, ALD, wmma::mem_row_major);
  }
  __syncwarp();
  {
    float* sr = &ss[r_el * ALD + cb];
    const int lim = i0 + r_el - j0 - cb;
    if (needmask) {
#pragma unroll
      for (int c = 0; c < 32; c += 4) {
        float4 s4 = *(float4*)&sr[c];
        float p0 = __expf(s4.x), p1 = __expf(s4.y);
        float p2 = __expf(s4.z), p3 = __expf(s4.w);
        p0 = (c + 0 <= lim) ? p0 : 0.0f;
        p1 = (c + 1 <= lim) ? p1 : 0.0f;
        p2 = (c + 2 <= lim) ? p2 : 0.0f;
        p3 = (c + 3 <= lim) ? p3 : 0.0f;
        lacc += (p0 + p1) + (p2 + p3);
        s4.x = tf32r(p0); s4.y = tf32r(p1); s4.z = tf32r(p2); s4.w = tf32r(p3);
        *(float4*)&sr[c] = s4;
      }
    } else {
#pragma unroll
      for (int c = 0; c < 32; c += 4) {
        float4 s4 = *(float4*)&sr[c];
        float p0 = __expf(s4.x), p1 = __expf(s4.y);
        float p2 = __expf(s4.z), p3 = __expf(s4.w);
        lacc += (p0 + p1) + (p2 + p3);
        s4.x = tf32r(p0); s4.y = tf32r(p1); s4.z = tf32r(p2); s4.w = tf32r(p3);
        *(float4*)&sr[c] = s4;
      }
    }
  }
  __syncwarp();
#pragma unroll
  for (int kk = 0; kk < 64; kk += 8) {
    wmma::fragment<wmma::matrix_a, 16, 16, 8, wmma::precision::tf32, wmma::row_major> pa;
    wmma::load_matrix_sync(pa, &ss[wr * ALD + kk], ALD);
#pragma unroll
    for (int dt = 0; dt < 4; dt++) {
      wmma::fragment<wmma::matrix_b, 16, 16, 8, wmma::precision::tf32, wmma::row_major> vb;
      wmma::load_matrix_sync(vb, &vsd[kk * ALD + dt * 16], ALD);
      wmma::mma_sync(O[dt], pa, vb, O[dt]);
    }
  }
  __syncwarp();
}

#define ATTN_SMEM ((2 * 128 * ALD + 2 * KV_STG + 128 * ALD) * (int)sizeof(float))  // 208,896

__global__ __launch_bounds__(256) void attn_kernel(
    const float* __restrict__ lam_p, float* __restrict__ attn_out) {
  extern __shared__ float sm[];
  float* q1s = sm;                    // 128 x ALD
  float* q2s = q1s + 128 * ALD;       // 128 x ALD
  float* kvs = q2s + 128 * ALD;       // 2 x (k1|k2|v, each 64 x ALD)
  float* ss  = kvs + 2 * KV_STG;      // 128 x ALD
  const uint32_t sQ  = smem_u32(q1s);
  const uint32_t sKV = smem_u32(kvs);

  const int tid  = threadIdx.x;
  const int warp = tid >> 5;
  const int wr   = warp * 16;
  const int b    = blockIdx.z;
  const int h    = blockIdx.y;
  const int i0   = (int)(gridDim.x - 1 - blockIdx.x) * 128;  // heavy first
  const float lamc = fminf(fmaxf(lam_p[h], 0.0f), 1.0f);

  const float* base = g_qkv + (size_t)b * NT * QKVN + h * (5 * ND);

#define ATT_ISSUE_KV(j0, bufi)                                                 \
  {                                                                            \
    uint32_t dstb = sKV + (uint32_t)(bufi) * (KV_STG * 4);                     \
    _Pragma("unroll") for (int i = 0; i < 12; i++) {                           \
      int f = tid + i * 256;                                                   \
      int mat = f >> 10, r = (f >> 4) & 63, c4 = (f & 15) * 4;                 \
      CP_ASYNC16(dstb + (uint32_t)(mat * 64 * ALD + r * ALD + c4) * 4,         \
                 &base[(size_t)((j0) + r) * QKVN + (2 + mat) * ND + c4]);      \
    }                                                                          \
    CP_COMMIT();                                                               \
  }

  // Prologue: group0 = Q + KV tile0 ; group1 = KV tile1
  {
#pragma unroll
    for (int i = 0; i < 16; i++) {
      int f = tid + i * 256;
      int mat = f >> 11, r = (f >> 4) & 127, c4 = (f & 15) * 4;
      CP_ASYNC16(sQ + (uint32_t)(mat * 128 * ALD + r * ALD + c4) * 4,
                 &base[(size_t)(i0 + r) * QKVN + mat * ND + c4]);
    }
    uint32_t dstb = sKV;
#pragma unroll
    for (int i = 0; i < 12; i++) {
      int f = tid + i * 256;
      int mat = f >> 10, r = (f >> 4) & 63, c4 = (f & 15) * 4;
      CP_ASYNC16(dstb + (uint32_t)(mat * 64 * ALD + r * ALD + c4) * 4,
                 &base[(size_t)r * QKVN + (2 + mat) * ND + c4]);
    }
    CP_COMMIT();
    ATT_ISSUE_KV(64, 1);
  }

  FragAcc O1[4], O2[4];
#pragma unroll
  for (int i = 0; i < 4; i++) {
    wmma::fill_fragment(O1[i], 0.0f);
    wmma::fill_fragment(O2[i], 0.0f);
  }
  float l1acc = 0.0f, l2acc = 0.0f;
  const int r_el = tid >> 1;
  const int cb   = (tid & 1) * 32;

  const int ntiles = i0 / 64 + 2;
  for (int t = 0; t < ntiles; t++) {
    const int j0 = t * 64;
    cp_wait(t == ntiles - 1);
    __syncthreads();

    const float* kb = kvs + (t & 1) * KV_STG;
    const float* vb = kb + 2 * 64 * ALD;
    const bool needmask = (j0 + 63 > i0);
    attn_pass(q1s, kb, vb, ss, O1, l1acc, wr, r_el, cb, i0, j0, needmask);
    attn_pass(q2s, kb + 64 * ALD, vb, ss, O2, l2acc, wr, r_el, cb, i0, j0, needmask);
    __syncthreads();
    if (t + 2 < ntiles) ATT_ISSUE_KV((t + 2) * 64, t & 1);
  }

  // Park O1 in ss strip, O2 in kv-buf0 strip (k1|k2 = 128 contiguous rows)
#pragma unroll
  for (int dt = 0; dt < 4; dt++) {
    wmma::store_matrix_sync(&ss[wr * ALD + dt * 16], O1[dt], ALD, wmma::mem_row_major);
    wmma::store_matrix_sync(&kvs[wr * ALD + dt * 16], O2[dt], ALD, wmma::mem_row_major);
  }
  __syncwarp();

  const float l1 = l1acc + __shfl_xor_sync(0xFFFFFFFFu, l1acc, 1);
  const float l2 = l2acc + __shfl_xor_sync(0xFFFFFFFFu, l2acc, 1);
  const float inv1 = 1.0f / l1;
  const float inv2 = lamc / l2;

  const float* o1r = &ss[r_el * ALD + cb];
  const float* o2r = &kvs[r_el * ALD + cb];
  float* outp = attn_out + (size_t)(b * NT + i0 + r_el) * NDM + h * ND + cb;
#pragma unroll
  for (int c = 0; c < 32; c += 4) {
    float4 a = *(const float4*)&o1r[c];
    float4 d = *(const float4*)&o2r[c];
    float4 o;
    o.x = tf32r(a.x * inv1 - d.x * inv2);
    o.y = tf32r(a.y * inv1 - d.y * inv2);
    o.z = tf32r(a.z * inv1 - d.z * inv2);
    o.w = tf32r(a.w * inv1 - d.w * inv2);
    *(float4*)&outp[c] = o;
  }
}

// ---------------------------------------------------------------------------
extern "C" void kernel_launch(void* const* d_in, const int* in_sizes, int n_in,
                              void* d_out, int out_size) {
  const float* x    = (const float*)d_in[0];
  // d_in[1] = mask: exact causal additive mask; handled analytically.
  const float* Wqkv = (const float*)d_in[2];
  const float* Wout = (const float*)d_in[3];
  const float* lam  = (const float*)d_in[4];
  float* out = (float*)d_out;

  float *qkv_d, *attn_d, *x_d, *wq_d, *wo_d;
  cudaGetSymbolAddress((void**)&qkv_d, g_qkv);
  cudaGetSymbolAddress((void**)&attn_d, g_attn);
  cudaGetSymbolAddress((void**)&x_d, g_x);
  cudaGetSymbolAddress((void**)&wq_d, g_wq);
  cudaGetSymbolAddress((void**)&wo_d, g_wo);

  cudaFuncSetAttribute(gemm_tc, cudaFuncAttributeMaxDynamicSharedMemorySize, GEMM_SMEM);
  cudaFuncSetAttribute(attn_kernel, cudaFuncAttributeMaxDynamicSharedMemorySize, ATTN_SMEM);

  // 0) pre-round inputs to tf32
  {
    int n4x = BTOT * NDM / 4;
    round_tf32_kernel<<<n4x / 256, 256>>>(x, x_d, n4x);
    int n4q = NDM * QKVN / 4;
    round_tf32_kernel<<<n4q / 256, 256>>>(Wqkv, wq_d, n4q);
    int n4o = NDM * NDM / 4;
    round_tf32_kernel<<<n4o / 256, 256>>>(Wout, wo_d, n4o);
  }

  // 1) qkv = x @ W_qkv  (epilogue: scale q cols + tf32 round)
  {
    dim3 grid(QKVN / TNN, BTOT / TMM);  // (40, 32)
    gemm_tc<<<grid, 256, GEMM_SMEM>>>(x_d, wq_d, qkv_d, BTOT, QKVN, NDM, 1);
  }

  // 2) differential attention (single pass, cp.async pipelined)
  {
    dim3 grid(NT / 128, NH, NBATCH);  // (16, 16, 2)
    attn_kernel<<<grid, 256, ATTN_SMEM>>>(lam, attn_d);
  }

  // 3) out = attn @ W_out
  {
    dim3 grid(NDM / TNN, BTOT / TMM);  // (8, 32)
    gemm_tc<<<grid, 256, GEMM_SMEM>>>(attn_d, wo_d, out, BTOT, NDM, NDM, 0);
  }
}

// round 5
// speedup vs baseline: 2.1661x; 1.1651x over previous
#include <cuda_runtime.h>
#include <mma.h>
#include <math.h>
#include <cstdint>

using namespace nvcuda;

#define NBATCH 2
#define NT     2048
#define NDM    1024
#define NH     16
#define ND     64
#define QKVN   (NH * 5 * ND)   // 5120
#define BTOT   (NBATCH * NT)   // 4096

// Scratch (device-global; allocation-free per harness rules)
__device__ float g_qkv[(size_t)BTOT * QKVN];    // tf32-rounded, q-scaled
__device__ float g_attn[(size_t)BTOT * NDM];    // tf32-rounded
__device__ float g_x  [(size_t)BTOT * NDM];     // tf32-rounded x
__device__ float g_wq [(size_t)NDM * QKVN];     // tf32-rounded W_qkv
__device__ float g_wo [(size_t)NDM * NDM];      // tf32-rounded W_out

__device__ __forceinline__ float tf32r(float x) { return wmma::__float_to_tf32(x); }

__device__ __forceinline__ uint32_t smem_u32(const void* p) {
  uint32_t a;
  asm("{ .reg .u64 t; cvta.to.shared.u64 t, %1; cvt.u32.u64 %0, t; }"
      : "=r"(a) : "l"(p));
  return a;
}

#define CP_ASYNC16(dst, src) \
  asm volatile("cp.async.cg.shared.global [%0], [%1], 16;" :: "r"(dst), "l"(src))
#define CP_COMMIT() asm volatile("cp.async.commit_group;" ::: "memory")
#define CP_WAIT(n)  asm volatile("cp.async.wait_group %0;" :: "n"(n) : "memory")

// ---------------------------------------------------------------------------
// tf32 pre-round kernel (float4 grid-stride)
// ---------------------------------------------------------------------------
__global__ void round_tf32_kernel(const float* __restrict__ in,
                                  float* __restrict__ out, int n4) {
  int i = blockIdx.x * blockDim.x + threadIdx.x;
  if (i < n4) {
    float4 v = ((const float4*)in)[i];
    v.x = tf32r(v.x); v.y = tf32r(v.y); v.z = tf32r(v.z); v.w = tf32r(v.w);
    ((float4*)out)[i] = v;
  }
}

// ---------------------------------------------------------------------------
// TF32 wmma GEMM, cp.async 3-stage (unchanged from R4 — proven 610us/150us).
// ---------------------------------------------------------------------------
#define TMM 128
#define TNN 128
#define TKK 32
#define LDA 36
#define LDB 132
#define A_STG (TMM * LDA)
#define B_STG (TKK * LDB)
#define GEMM_SMEM (3 * (A_STG + B_STG) * (int)sizeof(float))
#define LDS 132

__global__ __launch_bounds__(256, 2) void gemm_tc(
    const float* __restrict__ A, const float* __restrict__ B,
    float* __restrict__ C, int M, int N, int K, int mode) {
  extern __shared__ float smg[];
  float* Asm = smg;
  float* Bsm = smg + 3 * A_STG;
  const uint32_t sA = smem_u32(Asm);
  const uint32_t sB = smem_u32(Bsm);

  const int tid  = threadIdx.x;
  const int warp = tid >> 5;
  const int wm   = warp & 1;
  const int wn   = warp >> 1;
  const int bm   = blockIdx.y * TMM;
  const int bn   = blockIdx.x * TNN;

#define G_ISSUE(k0, s)                                                         \
  {                                                                            \
    uint32_t aB = sA + (uint32_t)(s) * (A_STG * 4);                            \
    uint32_t bB = sB + (uint32_t)(s) * (B_STG * 4);                            \
    _Pragma("unroll") for (int j = 0; j < 4; j++) {                            \
      int f = tid + j * 256;                                                   \
      int r = f >> 3, c4 = (f & 7) * 4;                                        \
      CP_ASYNC16(aB + (uint32_t)(r * LDA + c4) * 4,                            \
                 &A[(size_t)(bm + r) * K + (k0) + c4]);                        \
    }                                                                          \
    _Pragma("unroll") for (int j = 0; j < 4; j++) {                            \
      int f = tid + j * 256;                                                   \
      int r = f >> 5, c4 = (f & 31) * 4;                                       \
      CP_ASYNC16(bB + (uint32_t)(r * LDB + c4) * 4,                            \
                 &B[(size_t)((k0) + r) * N + bn + c4]);                        \
    }                                                                          \
    CP_COMMIT();                                                               \
  }

  wmma::fragment<wmma::accumulator, 16, 16, 8, float> acc[4][2];
#pragma unroll
  for (int i = 0; i < 4; i++)
#pragma unroll
    for (int j = 0; j < 2; j++) wmma::fill_fragment(acc[i][j], 0.0f);

  G_ISSUE(0, 0);
  G_ISSUE(TKK, 1);

  const int niter = K / TKK;
  for (int it = 0; it < niter; it++) {
    if (it == niter - 1) CP_WAIT(0); else CP_WAIT(1);
    __syncthreads();
    if (it + 2 < niter) G_ISSUE((it + 2) * TKK, (it + 2) % 3);

    const float* As_ = Asm + (it % 3) * A_STG;
    const float* Bs_ = Bsm + (it % 3) * B_STG;
#pragma unroll
    for (int kk = 0; kk < TKK; kk += 8) {
      wmma::fragment<wmma::matrix_a, 16, 16, 8, wmma::precision::tf32, wmma::row_major> af[4];
      wmma::fragment<wmma::matrix_b, 16, 16, 8, wmma::precision::tf32, wmma::row_major> bf[2];
#pragma unroll
      for (int i = 0; i < 4; i++)
        wmma::load_matrix_sync(af[i], &As_[(wm * 64 + i * 16) * LDA + kk], LDA);
#pragma unroll
      for (int j = 0; j < 2; j++)
        wmma::load_matrix_sync(bf[j], &Bs_[kk * LDB + wn * 32 + j * 16], LDB);
#pragma unroll
      for (int i = 0; i < 4; i++)
#pragma unroll
        for (int j = 0; j < 2; j++)
          wmma::mma_sync(acc[i][j], af[i], bf[j], acc[i][j]);
    }
  }

  __syncthreads();
#pragma unroll
  for (int i = 0; i < 4; i++)
#pragma unroll
    for (int j = 0; j < 2; j++)
      wmma::store_matrix_sync(&smg[(wm * 64 + i * 16) * LDS + wn * 32 + j * 16],
                              acc[i][j], LDS, wmma::mem_row_major);
  __syncthreads();

#pragma unroll
  for (int i = 0; i < 16; i++) {
    int f = tid + i * 256;
    int r = f >> 5, c4 = (f & 31) * 4;
    float4 v = *(const float4*)&smg[r * LDS + c4];
    if (mode == 1) {
      int gc = bn + c4;
      float s = ((gc % 320) < 128) ? 0.125f : 1.0f;
      v.x = tf32r(v.x * s); v.y = tf32r(v.y * s);
      v.z = tf32r(v.z * s); v.w = tf32r(v.w * s);
    }
    *(float4*)&C[(size_t)(bm + r) * N + bn + c4] = v;
  }
}

// ---------------------------------------------------------------------------
// Single-pass differential attention.
// Q fragments register-resident; dual S buffers; single V fetch feeds both
// PV accumulations. 256 threads, 128-query tile, 64-key tiles, 2 KV stages.
// ---------------------------------------------------------------------------
#define ALD 68
#define KV_STG (3 * 64 * ALD)  // k1|k2|v per stage

using FragAcc = wmma::fragment<wmma::accumulator, 16, 16, 8, float>;
using FragA   = wmma::fragment<wmma::matrix_a, 16, 16, 8, wmma::precision::tf32, wmma::row_major>;
using FragBc  = wmma::fragment<wmma::matrix_b, 16, 16, 8, wmma::precision::tf32, wmma::col_major>;
using FragBr  = wmma::fragment<wmma::matrix_b, 16, 16, 8, wmma::precision::tf32, wmma::row_major>;

#define ATTN_SMEM ((2 * KV_STG + 2 * 128 * ALD) * (int)sizeof(float))  // 174,080 B

__global__ __launch_bounds__(256) void attn_kernel(
    const float* __restrict__ lam_p, float* __restrict__ attn_out) {
  extern __shared__ float sm[];
  float* kvs = sm;                    // 2 x (k1|k2|v, each 64 x ALD)
  float* ss1 = kvs + 2 * KV_STG;      // 128 x ALD (Q1 staging, then S1/P1, then O1)
  float* ss2 = ss1 + 128 * ALD;       // 128 x ALD (Q2 staging, then S2/P2, then O2)
  const uint32_t sKV = smem_u32(kvs);
  const uint32_t sS1 = smem_u32(ss1);
  const uint32_t sS2 = smem_u32(ss2);

  const int tid  = threadIdx.x;
  const int warp = tid >> 5;
  const int wr   = warp * 16;
  const int b    = blockIdx.z;
  const int h    = blockIdx.y;
  const int i0   = (int)(gridDim.x - 1 - blockIdx.x) * 128;  // heavy first
  const float lamc = fminf(fmaxf(lam_p[h], 0.0f), 1.0f);

  const float* base = g_qkv + (size_t)b * NT * QKVN + h * (5 * ND);

#define ATT_ISSUE_KV(j0, bufi)                                                 \
  {                                                                            \
    uint32_t dstb = sKV + (uint32_t)(bufi) * (KV_STG * 4);                     \
    _Pragma("unroll") for (int i = 0; i < 12; i++) {                           \
      int f = tid + i * 256;                                                   \
      int mat = f >> 10, r = (f >> 4) & 63, c4 = (f & 15) * 4;                 \
      CP_ASYNC16(dstb + (uint32_t)(mat * 64 * ALD + r * ALD + c4) * 4,         \
                 &base[(size_t)((j0) + r) * QKVN + (2 + mat) * ND + c4]);      \
    }                                                                          \
    CP_COMMIT();                                                               \
  }

  // Prologue: G0 = Q1->ss1, Q2->ss2 ; G1 = KV0 ; G2 = KV1
  {
#pragma unroll
    for (int i = 0; i < 16; i++) {
      int f = tid + i * 256;
      int mat = f >> 11, r = (f >> 4) & 127, c4 = (f & 15) * 4;
      CP_ASYNC16((mat ? sS2 : sS1) + (uint32_t)(r * ALD + c4) * 4,
                 &base[(size_t)(i0 + r) * QKVN + mat * ND + c4]);
    }
    CP_COMMIT();
    ATT_ISSUE_KV(0, 0);
    ATT_ISSUE_KV(64, 1);
  }

  // Q fragments -> registers (freed ss1/ss2 for S use afterwards)
  FragA q1f[8], q2f[8];
  CP_WAIT(2);
  __syncthreads();
#pragma unroll
  for (int kk = 0; kk < 8; kk++) {
    wmma::load_matrix_sync(q1f[kk], &ss1[wr * ALD + kk * 8], ALD);
    wmma::load_matrix_sync(q2f[kk], &ss2[wr * ALD + kk * 8], ALD);
  }

  FragAcc O1[4], O2[4];
#pragma unroll
  for (int i = 0; i < 4; i++) {
    wmma::fill_fragment(O1[i], 0.0f);
    wmma::fill_fragment(O2[i], 0.0f);
  }
  float l1acc = 0.0f, l2acc = 0.0f;
  const int r_el = tid >> 1;
  const int cb   = (tid & 1) * 32;

  const int ntiles = i0 / 64 + 2;
  for (int t = 0; t < ntiles; t++) {
    const int j0 = t * 64;
    if (t == ntiles - 1) CP_WAIT(0); else CP_WAIT(1);
    __syncthreads();  // KV tile t visible; also guards ss reuse (Q frags read / prev parked)

    const float* kb1 = kvs + (t & 1) * KV_STG;
    const float* kb2 = kb1 + 64 * ALD;
    const float* vb_ = kb1 + 2 * 64 * ALD;

    // ---- S1, S2 strips ----
#pragma unroll
    for (int jt = 0; jt < 4; jt++) {
      FragAcc s1a, s2a;
      wmma::fill_fragment(s1a, 0.0f);
      wmma::fill_fragment(s2a, 0.0f);
#pragma unroll
      for (int kk = 0; kk < 8; kk++) {
        FragBc b1, b2;
        wmma::load_matrix_sync(b1, &kb1[(jt * 16) * ALD + kk * 8], ALD);
        wmma::load_matrix_sync(b2, &kb2[(jt * 16) * ALD + kk * 8], ALD);
        wmma::mma_sync(s1a, q1f[kk], b1, s1a);
        wmma::mma_sync(s2a, q2f[kk], b2, s2a);
      }
      wmma::store_matrix_sync(&ss1[wr * ALD + jt * 16], s1a, ALD, wmma::mem_row_major);
      wmma::store_matrix_sync(&ss2[wr * ALD + jt * 16], s2a, ALD, wmma::mem_row_major);
    }
    __syncwarp();

    // ---- exp + causal mask + row-sum partials (both matrices) ----
    {
      float* sr1 = &ss1[r_el * ALD + cb];
      float* sr2 = &ss2[r_el * ALD + cb];
      const int lim = i0 + r_el - j0 - cb;
      if (j0 + 63 > i0) {
#pragma unroll
        for (int c = 0; c < 32; c += 4) {
          float4 a4 = *(float4*)&sr1[c];
          float4 b4 = *(float4*)&sr2[c];
          float p0 = __expf(a4.x), p1 = __expf(a4.y), p2 = __expf(a4.z), p3 = __expf(a4.w);
          float u0 = __expf(b4.x), u1 = __expf(b4.y), u2 = __expf(b4.z), u3 = __expf(b4.w);
          if (c + 0 > lim) { p0 = 0.0f; u0 = 0.0f; }
          if (c + 1 > lim) { p1 = 0.0f; u1 = 0.0f; }
          if (c + 2 > lim) { p2 = 0.0f; u2 = 0.0f; }
          if (c + 3 > lim) { p3 = 0.0f; u3 = 0.0f; }
          l1acc += (p0 + p1) + (p2 + p3);
          l2acc += (u0 + u1) + (u2 + u3);
          a4.x = tf32r(p0); a4.y = tf32r(p1); a4.z = tf32r(p2); a4.w = tf32r(p3);
          b4.x = tf32r(u0); b4.y = tf32r(u1); b4.z = tf32r(u2); b4.w = tf32r(u3);
          *(float4*)&sr1[c] = a4;
          *(float4*)&sr2[c] = b4;
        }
      } else {
#pragma unroll
        for (int c = 0; c < 32; c += 4) {
          float4 a4 = *(float4*)&sr1[c];
          float4 b4 = *(float4*)&sr2[c];
          float p0 = __expf(a4.x), p1 = __expf(a4.y), p2 = __expf(a4.z), p3 = __expf(a4.w);
          float u0 = __expf(b4.x), u1 = __expf(b4.y), u2 = __expf(b4.z), u3 = __expf(b4.w);
          l1acc += (p0 + p1) + (p2 + p3);
          l2acc += (u0 + u1) + (u2 + u3);
          a4.x = tf32r(p0); a4.y = tf32r(p1); a4.z = tf32r(p2); a4.w = tf32r(p3);
          b4.x = tf32r(u0); b4.y = tf32r(u1); b4.z = tf32r(u2); b4.w = tf32r(u3);
          *(float4*)&sr1[c] = a4;
          *(float4*)&sr2[c] = b4;
        }
      }
    }
    __syncwarp();

    // ---- PV: single V fetch feeds both accumulations ----
#pragma unroll
    for (int kk = 0; kk < 8; kk++) {
      FragA pa1, pa2;
      wmma::load_matrix_sync(pa1, &ss1[wr * ALD + kk * 8], ALD);
      wmma::load_matrix_sync(pa2, &ss2[wr * ALD + kk * 8], ALD);
#pragma unroll
      for (int dt = 0; dt < 4; dt++) {
        FragBr vb;
        wmma::load_matrix_sync(vb, &vb_[(kk * 8) * ALD + dt * 16], ALD);
        wmma::mma_sync(O1[dt], pa1, vb, O1[dt]);
        wmma::mma_sync(O2[dt], pa2, vb, O2[dt]);
      }
    }
    __syncthreads();  // all warps done with KV buffer before refill
    if (t + 2 < ntiles) ATT_ISSUE_KV((t + 2) * 64, t & 1);
  }

  // Park O1 in ss1 strip, O2 in ss2 strip (warp-private rows)
#pragma unroll
  for (int dt = 0; dt < 4; dt++) {
    wmma::store_matrix_sync(&ss1[wr * ALD + dt * 16], O1[dt], ALD, wmma::mem_row_major);
    wmma::store_matrix_sync(&ss2[wr * ALD + dt * 16], O2[dt], ALD, wmma::mem_row_major);
  }
  __syncwarp();

  const float l1 = l1acc + __shfl_xor_sync(0xFFFFFFFFu, l1acc, 1);
  const float l2 = l2acc + __shfl_xor_sync(0xFFFFFFFFu, l2acc, 1);
  const float inv1 = 1.0f / l1;
  const float inv2 = lamc / l2;

  const float* o1r = &ss1[r_el * ALD + cb];
  const float* o2r = &ss2[r_el * ALD + cb];
  float* outp = attn_out + (size_t)(b * NT + i0 + r_el) * NDM + h * ND + cb;
#pragma unroll
  for (int c = 0; c < 32; c += 4) {
    float4 a = *(const float4*)&o1r[c];
    float4 d = *(const float4*)&o2r[c];
    float4 o;
    o.x = tf32r(a.x * inv1 - d.x * inv2);
    o.y = tf32r(a.y * inv1 - d.y * inv2);
    o.z = tf32r(a.z * inv1 - d.z * inv2);
    o.w = tf32r(a.w * inv1 - d.w * inv2);
    *(float4*)&outp[c] = o;
  }
}

// ---------------------------------------------------------------------------
extern "C" void kernel_launch(void* const* d_in, const int* in_sizes, int n_in,
                              void* d_out, int out_size) {
  const float* x    = (const float*)d_in[0];
  // d_in[1] = mask: exact causal additive mask; handled analytically.
  const float* Wqkv = (const float*)d_in[2];
  const float* Wout = (const float*)d_in[3];
  const float* lam  = (const float*)d_in[4];
  float* out = (float*)d_out;

  float *qkv_d, *attn_d, *x_d, *wq_d, *wo_d;
  cudaGetSymbolAddress((void**)&qkv_d, g_qkv);
  cudaGetSymbolAddress((void**)&attn_d, g_attn);
  cudaGetSymbolAddress((void**)&x_d, g_x);
  cudaGetSymbolAddress((void**)&wq_d, g_wq);
  cudaGetSymbolAddress((void**)&wo_d, g_wo);

  cudaFuncSetAttribute(gemm_tc, cudaFuncAttributeMaxDynamicSharedMemorySize, GEMM_SMEM);
  cudaFuncSetAttribute(attn_kernel, cudaFuncAttributeMaxDynamicSharedMemorySize, ATTN_SMEM);

  // 0) pre-round inputs to tf32
  {
    int n4x = BTOT * NDM / 4;
    round_tf32_kernel<<<n4x / 256, 256>>>(x, x_d, n4x);
    int n4q = NDM * QKVN / 4;
    round_tf32_kernel<<<n4q / 256, 256>>>(Wqkv, wq_d, n4q);
    int n4o = NDM * NDM / 4;
    round_tf32_kernel<<<n4o / 256, 256>>>(Wout, wo_d, n4o);
  }

  // 1) qkv = x @ W_qkv  (epilogue: scale q cols + tf32 round)
  {
    dim3 grid(QKVN / TNN, BTOT / TMM);  // (40, 32)
    gemm_tc<<<grid, 256, GEMM_SMEM>>>(x_d, wq_d, qkv_d, BTOT, QKVN, NDM, 1);
  }

  // 2) differential attention
  {
    dim3 grid(NT / 128, NH, NBATCH);  // (16, 16, 2)
    attn_kernel<<<grid, 256, ATTN_SMEM>>>(lam, attn_d);
  }

  // 3) out = attn @ W_out
  {
    dim3 grid(NDM / TNN, BTOT / TMM);  // (8, 32)
    gemm_tc<<<grid, 256, GEMM_SMEM>>>(attn_d, wo_d, out, BTOT, NDM, NDM, 0);
  }
}